// round 10
// baseline (speedup 1.0000x reference)
#include <cuda_runtime.h>

// BillehColumn GLIF3 simulation, forward only.
// Round 10: R8 base (conditional zero-store, block scatter queue, GPU-scope
// RED barrier) with warp-granular barrier arrive/poll (one __syncthreads per
// step instead of three) and parity queue counters (sync-free reset).
// R9's spike-counter skip reverted (regression: counter load serialized the
// critical path and never triggered).

#define Nn 100000
#define Rr 4
#define Ee 2000000
#define Tt 50
#define NRr (Nn * Rr)
#define SS 64                 // synapse slots per pre-neuron
#define OVF_CAP 4096
#define TPB 704               // 22 warps
#define NW (TPB / 32)
#define GRID 148              // 148 x 704 = 104192 >= N, one block per SM

__device__ float g_rec[2][NRr];
__device__ int   g_cnt[Nn];
__device__ int   g_ovf_cnt;
__device__ int   g_bar;
__device__ int2  g_syn[Nn * SS];       // {target slot, weight bits}
__device__ int   g_ovf_pre[OVF_CAP];
__device__ int   g_ovf_tgt[OVF_CAP];
__device__ float g_ovf_w[OVF_CAP];

__device__ __forceinline__ void bar_arrive_release() {
    asm volatile("red.release.gpu.global.add.s32 [%0], 1;"
                 :: "l"(&g_bar) : "memory");
}
__device__ __forceinline__ int bar_read_acquire() {
    int v;
    asm volatile("ld.acquire.gpu.global.s32 %0, [%1];"
                 : "=r"(v) : "l"(&g_bar) : "memory");
    return v;
}

// ---------------------------------------------------------------------------
// Zero rec buffers, counts, barrier state.
__global__ void k_zero() {
    int i = blockIdx.x * blockDim.x + threadIdx.x;
    int stride = gridDim.x * blockDim.x;
    float4* r4 = (float4*)g_rec;
    for (int j = i; j < (2 * NRr) / 4; j += stride)
        r4[j] = make_float4(0.f, 0.f, 0.f, 0.f);
    for (int j = i; j < Nn; j += stride)
        g_cnt[j] = 0;
    if (i == 0) { g_ovf_cnt = 0; g_bar = 0; }
}

// ---------------------------------------------------------------------------
// Single-pass synapse bucketing: slot = pre*SS + running count.
__global__ void k_fill(const int* __restrict__ pre,
                       const int* __restrict__ post,
                       const int* __restrict__ rcp,
                       const float* __restrict__ w) {
    int i = blockIdx.x * blockDim.x + threadIdx.x;   // quad index
    if (i >= Ee / 4) return;
    int4 p4 = ((const int4*)pre)[i];
    int4 q4 = ((const int4*)post)[i];
    int4 r4 = ((const int4*)rcp)[i];
    float4 w4 = ((const float4*)w)[i];

    int   ps[4] = {p4.x, p4.y, p4.z, p4.w};
    int   ts[4] = {q4.x * Rr + r4.x, q4.y * Rr + r4.y,
                   q4.z * Rr + r4.z, q4.w * Rr + r4.w};
    float ws[4] = {w4.x, w4.y, w4.z, w4.w};

#pragma unroll
    for (int k = 0; k < 4; k++) {
        int p = ps[k];
        int c = atomicAdd(&g_cnt[p], 1);
        if (c < SS) {
            g_syn[p * SS + c] = make_int2(ts[k], __float_as_int(ws[k]));
        } else {
            int o = atomicAdd(&g_ovf_cnt, 1);
            if (o < OVF_CAP) {
                g_ovf_pre[o] = p;
                g_ovf_tgt[o] = ts[k];
                g_ovf_w[o] = ws[k];
            }
        }
    }
}

// ---------------------------------------------------------------------------
// Persistent simulation. One thread per neuron; all state in registers.
__global__ void __launch_bounds__(TPB, 1) k_sim(
    const float* __restrict__ x_ext,
    float* __restrict__ out,
    const float* __restrict__ v0,
    const float* __restrict__ vth_,
    const float* __restrict__ vreset_,
    const float* __restrict__ tref_,
    const float* __restrict__ decay_,
    const float* __restrict__ cf_,
    const float* __restrict__ el_,
    const float* __restrict__ amps_,
    const float* __restrict__ ascd_,
    const float* __restrict__ syn_decay,
    const float* __restrict__ psc_init)
{
    __shared__ int q_base[TPB];
    __shared__ int q_m[TPB];
    __shared__ int q_n2[2];            // parity queue counters

    const int n = blockIdx.x * TPB + threadIdx.x;
    const bool act = (n < Nn);
    const int wid = threadIdx.x >> 5;
    const int lane = threadIdx.x & 31;

    const float4 sd = *(const float4*)syn_decay;
    const float4 pi = *(const float4*)psc_init;

    // Register-resident state.
    float v = 0.f, r = 0.f, z = 0.f;
    float2 a = make_float2(0.f, 0.f);
    float4 psc = make_float4(0.f, 0.f, 0.f, 0.f);
    float4 pr  = make_float4(0.f, 0.f, 0.f, 0.f);
    // Register-resident params.
    float vth = 1.f, rst = 0.f, trf = 0.f, dec = 0.f, cf = 0.f, el = 0.f;
    float2 am = make_float2(0.f, 0.f), ad = make_float2(0.f, 0.f);
    int sc = 0;
    float4 x = make_float4(0.f, 0.f, 0.f, 0.f);

    if (act) {
        v   = v0[n];
        vth = vth_[n];
        rst = vreset_[n] - vth;
        trf = tref_[n];
        dec = decay_[n];
        cf  = cf_[n];
        el  = el_[n];
        am  = *(const float2*)(&amps_[2 * n]);
        ad  = *(const float2*)(&ascd_[2 * n]);
        sc  = g_cnt[n];
        x   = __ldcs((const float4*)x_ext + n);   // step 0 input
    }
    const int m_syn = act ? ((sc < SS) ? sc : SS) : 0;
    const int base_syn = n * SS;

    if (threadIdx.x == 0) { q_n2[0] = 0; q_n2[1] = 0; }
    __syncthreads();

    for (int t = 0; t < Tt; t++) {
        const int p = t & 1;
        float* rec_cur = g_rec[p];
        float* rec_nxt = g_rec[p ^ 1];

        float zn = 0.f;
        if (act) {
            // L2-coherent read of this neuron's rec slots; zero only if dirty.
            float4 rec = __ldcg((const float4*)(rec_cur + 4 * n));
            if (rec.x != 0.f || rec.y != 0.f || rec.z != 0.f || rec.w != 0.f)
                __stcg((float4*)(rec_cur + 4 * n),
                       make_float4(0.f, 0.f, 0.f, 0.f));

            float in0 = rec.x + x.x;
            float in1 = rec.y + x.y;
            float in2 = rec.z + x.z;
            float in3 = rec.w + x.w;

            // Prefetch next step's external input (hidden behind the barrier).
            if (t + 1 < Tt)
                x = __ldcs((const float4*)x_ext + (size_t)(t + 1) * Nn + n);

            float4 npr, npsc;
            npr.x = pr.x * sd.x + in0 * pi.x;
            npr.y = pr.y * sd.y + in1 * pi.y;
            npr.z = pr.z * sd.z + in2 * pi.z;
            npr.w = pr.w * sd.w + in3 * pi.w;
            npsc.x = psc.x * sd.x + sd.x * pr.x;
            npsc.y = psc.y * sd.y + sd.y * pr.y;
            npsc.z = psc.z * sd.z + sd.z * pr.z;
            npsc.w = psc.w * sd.w + sd.w * pr.w;
            psc = npsc;
            pr = npr;

            float psum = ((npsc.x + npsc.y) + npsc.z) + npsc.w;
            float input_current = psum + (a.x + a.y);   // OLD asc

            a.x = ad.x * a.x + z * am.x;
            a.y = ad.y * a.y + z * am.y;

            float nv = dec * v + cf * (input_current + el) + z * rst;
            float vsc = (nv - vth) / vth;

            zn = (vsc > 0.f) ? 1.f : 0.f;
            if (r > 0.f) zn = 0.f;
            r = fmaxf(r - 1.f + zn * trf, 0.f);
            v = nv;
            z = zn;

            __stcs(&out[(size_t)t * Nn + n], zn);

            // Publish spike into the block scatter queue (parity counter).
            if (zn != 0.f) {
                int idx = atomicAdd(&q_n2[p], 1);
                q_base[idx] = base_syn;
                q_m[idx] = m_syn;
            }
        }

        // Single block-wide sync per step: queue visible to all warps.
        __syncthreads();

        // Reset the opposite-parity counter for step t+1 (its consumers all
        // passed the previous grid barrier; ordered before our release-arrive).
        if (threadIdx.x == 0) q_n2[p ^ 1] = 0;

        // Block-cooperative scatter: warps round-robin over queue entries.
        {
            const int total = q_n2[p];
            for (int i = wid; i < total; i += NW) {
                int b = q_base[i];
                int m = q_m[i];
                for (int s = lane; s < m; s += 32) {
                    int2 e = g_syn[b + s];
                    atomicAdd(&rec_nxt[e.x], __int_as_float(e.y));
                }
            }
            // Overflow entries (practically never taken).
            if (zn != 0.f && sc > SS) {
                int oc = g_ovf_cnt;
                if (oc > OVF_CAP) oc = OVF_CAP;
                for (int o = 0; o < oc; o++) {
                    if (g_ovf_pre[o] == n)
                        atomicAdd(&rec_nxt[g_ovf_tgt[o]], g_ovf_w[o]);
                }
            }
        }

        // Warp-granular grid barrier (skip after final step).
        if (t + 1 < Tt) {
            __syncwarp();
            if (lane == 0) {
                bar_arrive_release();          // release: our scatters visible
                const int target = GRID * NW * (t + 1);
                while (bar_read_acquire() < target) { }
            }
            __syncwarp();
        }
    }
}

// ---------------------------------------------------------------------------
extern "C" void kernel_launch(void* const* d_in, const int* in_sizes, int n_in,
                              void* d_out, int out_size) {
    const float* w_rec     = (const float*)d_in[0];
    const float* x_ext     = (const float*)d_in[1];
    const float* v0        = (const float*)d_in[2];
    const float* vth       = (const float*)d_in[3];
    const float* vreset    = (const float*)d_in[4];
    const float* tref      = (const float*)d_in[5];
    const float* decay     = (const float*)d_in[6];
    const float* cf        = (const float*)d_in[7];
    const float* el        = (const float*)d_in[8];
    const float* amps      = (const float*)d_in[9];
    const float* ascd      = (const float*)d_in[10];
    const float* syn_decay = (const float*)d_in[11];
    const float* psc_init  = (const float*)d_in[12];
    const int*   pre       = (const int*)d_in[13];
    const int*   post      = (const int*)d_in[14];
    const int*   rcp       = (const int*)d_in[15];
    float* out = (float*)d_out;

    k_zero<<<592, 256>>>();
    k_fill<<<(Ee / 4 + 255) / 256, 256>>>(pre, post, rcp, w_rec);
    k_sim<<<GRID, TPB>>>(x_ext, out, v0, vth, vreset, tref, decay, cf, el,
                         amps, ascd, syn_decay, psc_init);
}

// round 11
// speedup vs baseline: 3.1361x; 3.1361x over previous
#include <cuda_runtime.h>

// BillehColumn GLIF3 simulation, forward only.
// Round 11: R8 base (best @246us: conditional zero-store, block scatter
// queue, block-granular GPU-scope RED barrier) with:
//  - 2 syncthreads/step instead of 3: last-local-warp (smem counter) issues
//    the block's single global arrive as soon as scatter completes
//  - parity queue/arrival counters (sync-free resets)
// R10's warp-granular global arrive/poll reverted (3256-way single-line
// contention; 148 arrivers + 148 pollers is the right granularity).

#define Nn 100000
#define Rr 4
#define Ee 2000000
#define Tt 50
#define NRr (Nn * Rr)
#define SS 64                 // synapse slots per pre-neuron
#define OVF_CAP 4096
#define TPB 704               // 22 warps
#define NW (TPB / 32)
#define GRID 148              // 148 x 704 = 104192 >= N, one block per SM

__device__ float g_rec[2][NRr];
__device__ int   g_cnt[Nn];
__device__ int   g_ovf_cnt;
__device__ int   g_bar;
__device__ int2  g_syn[Nn * SS];       // {target slot, weight bits}
__device__ int   g_ovf_pre[OVF_CAP];
__device__ int   g_ovf_tgt[OVF_CAP];
__device__ float g_ovf_w[OVF_CAP];

__device__ __forceinline__ void bar_arrive_release() {
    asm volatile("red.release.gpu.global.add.s32 [%0], 1;"
                 :: "l"(&g_bar) : "memory");
}
__device__ __forceinline__ int bar_read_acquire() {
    int v;
    asm volatile("ld.acquire.gpu.global.s32 %0, [%1];"
                 : "=r"(v) : "l"(&g_bar) : "memory");
    return v;
}

// ---------------------------------------------------------------------------
// Zero rec buffers, counts, barrier state.
__global__ void k_zero() {
    int i = blockIdx.x * blockDim.x + threadIdx.x;
    int stride = gridDim.x * blockDim.x;
    float4* r4 = (float4*)g_rec;
    for (int j = i; j < (2 * NRr) / 4; j += stride)
        r4[j] = make_float4(0.f, 0.f, 0.f, 0.f);
    for (int j = i; j < Nn; j += stride)
        g_cnt[j] = 0;
    if (i == 0) { g_ovf_cnt = 0; g_bar = 0; }
}

// ---------------------------------------------------------------------------
// Single-pass synapse bucketing: slot = pre*SS + running count.
__global__ void k_fill(const int* __restrict__ pre,
                       const int* __restrict__ post,
                       const int* __restrict__ rcp,
                       const float* __restrict__ w) {
    int i = blockIdx.x * blockDim.x + threadIdx.x;   // quad index
    if (i >= Ee / 4) return;
    int4 p4 = ((const int4*)pre)[i];
    int4 q4 = ((const int4*)post)[i];
    int4 r4 = ((const int4*)rcp)[i];
    float4 w4 = ((const float4*)w)[i];

    int   ps[4] = {p4.x, p4.y, p4.z, p4.w};
    int   ts[4] = {q4.x * Rr + r4.x, q4.y * Rr + r4.y,
                   q4.z * Rr + r4.z, q4.w * Rr + r4.w};
    float ws[4] = {w4.x, w4.y, w4.z, w4.w};

#pragma unroll
    for (int k = 0; k < 4; k++) {
        int p = ps[k];
        int c = atomicAdd(&g_cnt[p], 1);
        if (c < SS) {
            g_syn[p * SS + c] = make_int2(ts[k], __float_as_int(ws[k]));
        } else {
            int o = atomicAdd(&g_ovf_cnt, 1);
            if (o < OVF_CAP) {
                g_ovf_pre[o] = p;
                g_ovf_tgt[o] = ts[k];
                g_ovf_w[o] = ws[k];
            }
        }
    }
}

// ---------------------------------------------------------------------------
// Persistent simulation. One thread per neuron; all state in registers.
__global__ void __launch_bounds__(TPB, 1) k_sim(
    const float* __restrict__ x_ext,
    float* __restrict__ out,
    const float* __restrict__ v0,
    const float* __restrict__ vth_,
    const float* __restrict__ vreset_,
    const float* __restrict__ tref_,
    const float* __restrict__ decay_,
    const float* __restrict__ cf_,
    const float* __restrict__ el_,
    const float* __restrict__ amps_,
    const float* __restrict__ ascd_,
    const float* __restrict__ syn_decay,
    const float* __restrict__ psc_init)
{
    __shared__ int q_base[TPB];
    __shared__ int q_m[TPB];
    __shared__ int q_n2[2];            // parity queue counters
    __shared__ int s_done[2];          // parity warp-arrival counters

    const int n = blockIdx.x * TPB + threadIdx.x;
    const bool act = (n < Nn);
    const int wid = threadIdx.x >> 5;
    const int lane = threadIdx.x & 31;

    const float4 sd = *(const float4*)syn_decay;
    const float4 pi = *(const float4*)psc_init;

    // Register-resident state.
    float v = 0.f, r = 0.f, z = 0.f;
    float2 a = make_float2(0.f, 0.f);
    float4 psc = make_float4(0.f, 0.f, 0.f, 0.f);
    float4 pr  = make_float4(0.f, 0.f, 0.f, 0.f);
    // Register-resident params.
    float vth = 1.f, rst = 0.f, trf = 0.f, dec = 0.f, cf = 0.f, el = 0.f;
    float2 am = make_float2(0.f, 0.f), ad = make_float2(0.f, 0.f);
    int sc = 0;
    float4 x = make_float4(0.f, 0.f, 0.f, 0.f);

    if (act) {
        v   = v0[n];
        vth = vth_[n];
        rst = vreset_[n] - vth;
        trf = tref_[n];
        dec = decay_[n];
        cf  = cf_[n];
        el  = el_[n];
        am  = *(const float2*)(&amps_[2 * n]);
        ad  = *(const float2*)(&ascd_[2 * n]);
        sc  = g_cnt[n];
        x   = __ldcs((const float4*)x_ext + n);   // step 0 input
    }
    const int m_syn = act ? ((sc < SS) ? sc : SS) : 0;
    const int base_syn = n * SS;

    if (threadIdx.x == 0) {
        q_n2[0] = 0; q_n2[1] = 0;
        s_done[0] = 0; s_done[1] = 0;
    }
    __syncthreads();

    for (int t = 0; t < Tt; t++) {
        const int p = t & 1;
        float* rec_cur = g_rec[p];
        float* rec_nxt = g_rec[p ^ 1];

        float zn = 0.f;
        if (act) {
            // L2-coherent read of this neuron's rec slots; zero only if dirty.
            float4 rec = __ldcg((const float4*)(rec_cur + 4 * n));
            if (rec.x != 0.f || rec.y != 0.f || rec.z != 0.f || rec.w != 0.f)
                __stcg((float4*)(rec_cur + 4 * n),
                       make_float4(0.f, 0.f, 0.f, 0.f));

            float in0 = rec.x + x.x;
            float in1 = rec.y + x.y;
            float in2 = rec.z + x.z;
            float in3 = rec.w + x.w;

            // Prefetch next step's external input (hidden behind the barrier).
            if (t + 1 < Tt)
                x = __ldcs((const float4*)x_ext + (size_t)(t + 1) * Nn + n);

            float4 npr, npsc;
            npr.x = pr.x * sd.x + in0 * pi.x;
            npr.y = pr.y * sd.y + in1 * pi.y;
            npr.z = pr.z * sd.z + in2 * pi.z;
            npr.w = pr.w * sd.w + in3 * pi.w;
            npsc.x = psc.x * sd.x + sd.x * pr.x;
            npsc.y = psc.y * sd.y + sd.y * pr.y;
            npsc.z = psc.z * sd.z + sd.z * pr.z;
            npsc.w = psc.w * sd.w + sd.w * pr.w;
            psc = npsc;
            pr = npr;

            float psum = ((npsc.x + npsc.y) + npsc.z) + npsc.w;
            float input_current = psum + (a.x + a.y);   // OLD asc

            a.x = ad.x * a.x + z * am.x;
            a.y = ad.y * a.y + z * am.y;

            float nv = dec * v + cf * (input_current + el) + z * rst;
            float vsc = (nv - vth) / vth;

            zn = (vsc > 0.f) ? 1.f : 0.f;
            if (r > 0.f) zn = 0.f;
            r = fmaxf(r - 1.f + zn * trf, 0.f);
            v = nv;
            z = zn;

            __stcs(&out[(size_t)t * Nn + n], zn);

            // Publish spike into the block scatter queue (parity counter).
            if (zn != 0.f) {
                int idx = atomicAdd(&q_n2[p], 1);
                q_base[idx] = base_syn;
                q_m[idx] = m_syn;
            }
        }

        // Sync A: queue visible to all warps.
        __syncthreads();

        // Reset opposite-parity queue counter for step t+1 (last readers
        // finished before the previous step's final sync).
        if (threadIdx.x == 0) q_n2[p ^ 1] = 0;

        // Block-cooperative scatter: warps round-robin over queue entries.
        {
            const int total = q_n2[p];
            for (int i = wid; i < total; i += NW) {
                int b = q_base[i];
                int m = q_m[i];
                for (int s = lane; s < m; s += 32) {
                    int2 e = g_syn[b + s];
                    atomicAdd(&rec_nxt[e.x], __int_as_float(e.y));
                }
            }
            // Overflow entries (practically never taken).
            if (zn != 0.f && sc > SS) {
                int oc = g_ovf_cnt;
                if (oc > OVF_CAP) oc = OVF_CAP;
                for (int o = 0; o < oc; o++) {
                    if (g_ovf_pre[o] == n)
                        atomicAdd(&rec_nxt[g_ovf_tgt[o]], g_ovf_w[o]);
                }
            }
        }

        // Grid barrier (skip after final step). Last local warp to finish
        // scatter issues the block's single global arrive; thread 0 polls.
        if (t + 1 < Tt) {
            __syncwarp();
            if (lane == 0) {
                int d = atomicAdd(&s_done[p], 1);
                if (d == NW - 1) {
                    s_done[p] = 0;             // reset for step t+2 (parity)
                    bar_arrive_release();      // release: block's scatters
                }
            }
            if (threadIdx.x == 0) {
                const int target = GRID * (t + 1);
                while (bar_read_acquire() < target) { }
            }
            // Sync B: all warps wait for thread 0's poll to pass.
            __syncthreads();
        }
    }
}

// ---------------------------------------------------------------------------
extern "C" void kernel_launch(void* const* d_in, const int* in_sizes, int n_in,
                              void* d_out, int out_size) {
    const float* w_rec     = (const float*)d_in[0];
    const float* x_ext     = (const float*)d_in[1];
    const float* v0        = (const float*)d_in[2];
    const float* vth       = (const float*)d_in[3];
    const float* vreset    = (const float*)d_in[4];
    const float* tref      = (const float*)d_in[5];
    const float* decay     = (const float*)d_in[6];
    const float* cf        = (const float*)d_in[7];
    const float* el        = (const float*)d_in[8];
    const float* amps      = (const float*)d_in[9];
    const float* ascd      = (const float*)d_in[10];
    const float* syn_decay = (const float*)d_in[11];
    const float* psc_init  = (const float*)d_in[12];
    const int*   pre       = (const int*)d_in[13];
    const int*   post      = (const int*)d_in[14];
    const int*   rcp       = (const int*)d_in[15];
    float* out = (float*)d_out;

    k_zero<<<592, 256>>>();
    k_fill<<<(Ee / 4 + 255) / 256, 256>>>(pre, post, rcp, w_rec);
    k_sim<<<GRID, TPB>>>(x_ext, out, v0, vth, vreset, tref, decay, cf, el,
                         amps, ascd, syn_decay, psc_init);
}